// round 6
// baseline (speedup 1.0000x reference)
#include <cuda_runtime.h>

#define NPROP 1024
#define NCLS  81
#define NC2   80        // foreground classes
#define KDET  100
#define FDIM  1024
#define IMG_W 1216.0f
#define IMG_H 800.0f
#define SCORE_TH 0.05f
#define NMS_TH 0.5f
#define BBOX_CLIP 4.135166556742356f   // log(1000/16)

#define MMASK 256       // bitmask-NMS fast path capacity
#define WMASK 4         // 256/64 words
#define NBIN  1024

// ---------- device scratch (statically zero-initialized at module load) ----------
__device__ float2 g_rowstats[NPROP];                 // (rowmax, rowsum)
__device__ float  g_cand_box[NC2 * NPROP * 4];       // flat f = c*NPROP + sorted_pos
__device__ int    g_cand_orig[NC2 * NPROP];
__device__ unsigned long long g_plist[NC2 * NPROP];  // packed kept candidates
__device__ int    g_pcnt;
__device__ int    g_stats_done;  // class blocks that finished rowstats
__device__ int    g_done;        // class blocks completed NMS
__device__ int    g_feat_flag;   // top-k selection published
__device__ int    g_feat_done;   // feat blocks completed (for end-of-run reset)
__device__ int    g_sel_orig[KDET];

// non-atomic L2-scope poll (writer publishes with atomic + __threadfence)
__device__ __forceinline__ int poll_int(const int* p) {
    int v;
    asm volatile("ld.volatile.global.s32 %0, [%1];" : "=r"(v) : "l"(p));
    return v;
}

// ---------- shared-memory union (max ~37.1 KB < 48 KB static limit) ----------
struct NmsView {
    unsigned long long key[NPROP];           // 8 KB
    float x1[NPROP], y1[NPROP], x2[NPROP], y2[NPROP], area[NPROP]; // 20 KB
    unsigned long long mask[MMASK * WMASK];  // 8 KB
    unsigned long long kw[WMASK];
    unsigned char keep[NPROP];               // 1 KB (fallback)
    int cnt;
};
struct TopkView {
    int hist[NBIN];                          // 4 KB
    int part[256];                           // 1 KB
    unsigned long long key[2048];            // 16 KB
    int B, cnt;
};
union SMemU { NmsView nms; TopkView tk; };

// ---------- bitonic sort (descending) ----------
__device__ __forceinline__ void bitonic_desc(unsigned long long* key, int Sp, int tid, int nthr) {
    for (int k = 2; k <= Sp; k <<= 1) {
        for (int j = k >> 1; j > 0; j >>= 1) {
            for (int i = tid; i < Sp; i += nthr) {
                int ixj = i ^ j;
                if (ixj > i) {
                    unsigned long long a = key[i], b = key[ixj];
                    bool descBlock = ((i & k) == 0);
                    if (descBlock ? (a < b) : (a > b)) { key[i] = b; key[ixj] = a; }
                }
            }
            __syncthreads();
        }
    }
}

// ---------- class-block: cooperative softmax rowstats, then join ----------
__device__ void run_rowstats_and_join(int c, int tid, const float* __restrict__ logits) {
    const int warp = tid >> 5, lane = tid & 31;
    // class block c handles rows {c + 80*j}; warp w takes j = w, w+8, ...
    for (int r = c + NC2 * warp; r < NPROP; r += NC2 * 8) {
        const float* lp = logits + (size_t)r * NCLS;
        float mx = -3.4e38f;
        for (int j = lane; j < NCLS; j += 32) mx = fmaxf(mx, lp[j]);
        for (int o = 16; o; o >>= 1) mx = fmaxf(mx, __shfl_xor_sync(0xffffffffu, mx, o));
        float sum = 0.0f;
        for (int j = lane; j < NCLS; j += 32) sum += expf(lp[j] - mx);
        for (int o = 16; o; o >>= 1) sum += __shfl_xor_sync(0xffffffffu, sum, o);
        if (lane == 0) g_rowstats[r] = make_float2(mx, sum);
    }
    __threadfence();
    __syncthreads();
    if (tid == 0) {
        atomicAdd(&g_stats_done, 1);
        while (poll_int(&g_stats_done) < NC2) __nanosleep(60);
    }
    __syncthreads();
    __threadfence();
}

// ---------- class-block: per-class NMS ----------
__device__ void run_class_nms(NmsView& sm, int c, int tid,
                              const float* __restrict__ logits,
                              const float* __restrict__ box_reg,
                              const float* __restrict__ proposals) {
    const int bd = 256;
    if (tid == 0) sm.cnt = 0;
    __syncthreads();

    // Phase A: score this class's column; compact valid entries
    for (int n = tid; n < NPROP; n += bd) {
        float2 st = g_rowstats[n];
        float l = logits[(size_t)n * NCLS + (c + 1)];
        float p = expf(l - st.x) / st.y;
        if (p > SCORE_TH) {
            int pos = atomicAdd(&sm.cnt, 1);
            sm.key[pos] = ((unsigned long long)__float_as_uint(p) << 32) |
                          (unsigned)(NPROP - 1 - n);   // lower n wins ties
        }
    }
    __syncthreads();
    const int M = sm.cnt;
    if (M > 0) {
        int Mp = 1; while (Mp < M) Mp <<= 1;
        for (int p = M + tid; p < Mp; p += bd) sm.key[p] = 0ULL;
        __syncthreads();

        // Phase B: bitonic sort descending
        if (M > 1) bitonic_desc(sm.key, Mp, tid, bd);

        // Phase C: decode + clip valid entries
        for (int p = tid; p < M; p += bd) {
            int n = (NPROP - 1) - (int)(sm.key[p] & 0xFFFFFFFFULL);
            float4 pb = __ldg((const float4*)proposals + n);
            float w = pb.z - pb.x + 1.0f, h = pb.w - pb.y + 1.0f;
            float cx = pb.x + 0.5f * w,  cy = pb.y + 0.5f * h;
            float4 r = __ldg((const float4*)(box_reg + (size_t)n * (NCLS * 4) + (c + 1) * 4));
            float dx = r.x / 10.0f, dy = r.y / 10.0f;
            float dw = fminf(r.z / 5.0f, BBOX_CLIP);
            float dh = fminf(r.w / 5.0f, BBOX_CLIP);
            float pcx = dx * w + cx, pcy = dy * h + cy;
            float pw = expf(dw) * w, ph = expf(dh) * h;
            float x1 = pcx - 0.5f * pw, y1 = pcy - 0.5f * ph;
            float x2 = pcx + 0.5f * pw - 1.0f, y2 = pcy + 0.5f * ph - 1.0f;
            x1 = fminf(fmaxf(x1, 0.0f), IMG_W - 1.0f);
            y1 = fminf(fmaxf(y1, 0.0f), IMG_H - 1.0f);
            x2 = fminf(fmaxf(x2, 0.0f), IMG_W - 1.0f);
            y2 = fminf(fmaxf(y2, 0.0f), IMG_H - 1.0f);
            sm.x1[p] = x1; sm.y1[p] = y1; sm.x2[p] = x2; sm.y2[p] = y2;
            sm.area[p] = (x2 - x1 + 1.0f) * (y2 - y1 + 1.0f);
            sm.keep[p] = 1;
        }
        __syncthreads();

        const bool fastpath = (M <= MMASK);
        if (fastpath) {
            // Phase D-fast: parallel suppression bitmask + single-thread bit reduce
            const int nwords = M * WMASK;
            for (int idx = tid; idx < nwords; idx += bd) {
                int i = idx >> 2, w = idx & 3;
                float xi1 = sm.x1[i], yi1 = sm.y1[i], xi2 = sm.x2[i], yi2 = sm.y2[i], ai = sm.area[i];
                unsigned long long bits = 0ULL;
                int jlo = w << 6;
                int jhi = jlo + 64; if (jhi > M) jhi = M;
                int j0 = (i + 1 > jlo) ? i + 1 : jlo;
                for (int j = j0; j < jhi; j++) {
                    float xx1 = fmaxf(xi1, sm.x1[j]);
                    float yy1 = fmaxf(yi1, sm.y1[j]);
                    float xx2 = fminf(xi2, sm.x2[j]);
                    float yy2 = fminf(yi2, sm.y2[j]);
                    float ww = fmaxf(xx2 - xx1 + 1.0f, 0.0f);
                    float hh = fmaxf(yy2 - yy1 + 1.0f, 0.0f);
                    float inter = ww * hh;
                    float iou = inter / (ai + sm.area[j] - inter);
                    if (iou > NMS_TH) bits |= 1ULL << (j - jlo);
                }
                sm.mask[idx] = bits;
            }
            __syncthreads();
            if (tid == 0) {
                unsigned long long kw0 = ~0ULL, kw1 = ~0ULL, kw2 = ~0ULL, kw3 = ~0ULL;
                for (int i = 0; i < M; i++) {
                    unsigned long long ow = (i < 64) ? kw0 : (i < 128) ? kw1 : (i < 192) ? kw2 : kw3;
                    if ((ow >> (i & 63)) & 1ULL) {
                        const unsigned long long* row = &sm.mask[i << 2];
                        kw0 &= ~row[0]; kw1 &= ~row[1]; kw2 &= ~row[2]; kw3 &= ~row[3];
                    }
                }
                sm.kw[0] = kw0; sm.kw[1] = kw1; sm.kw[2] = kw2; sm.kw[3] = kw3;
            }
            __syncthreads();
        } else {
            // Phase D-fallback: sequential barrier NMS (M > 256, statistically rare)
            for (int i = 0; i < M; i++) {
                if (sm.keep[i]) {
                    float xi1 = sm.x1[i], yi1 = sm.y1[i], xi2 = sm.x2[i], yi2 = sm.y2[i], ai = sm.area[i];
                    for (int j = i + 1 + tid; j < M; j += bd) {
                        if (sm.keep[j]) {
                            float xx1 = fmaxf(xi1, sm.x1[j]);
                            float yy1 = fmaxf(yi1, sm.y1[j]);
                            float xx2 = fminf(xi2, sm.x2[j]);
                            float yy2 = fminf(yi2, sm.y2[j]);
                            float ww = fmaxf(xx2 - xx1 + 1.0f, 0.0f);
                            float hh = fmaxf(yy2 - yy1 + 1.0f, 0.0f);
                            float inter = ww * hh;
                            float iou = inter / (ai + sm.area[j] - inter);
                            if (iou > NMS_TH) sm.keep[j] = 0;
                        }
                    }
                }
                __syncthreads();
            }
        }

        // Phase E: emit kept candidates
        for (int p = tid; p < M; p += bd) {
            bool kept = fastpath ? ((sm.kw[p >> 6] >> (p & 63)) & 1ULL) : (bool)sm.keep[p];
            if (kept) {
                int f = c * NPROP + p;
                unsigned long long key = sm.key[p];
                unsigned sbits = (unsigned)(key >> 32);
                int n = (NPROP - 1) - (int)(key & 0xFFFFFFFFULL);
                int gp = atomicAdd(&g_pcnt, 1);
                g_plist[gp] = ((unsigned long long)sbits << 32) | (unsigned)(0x7FFFFFFF - f);
                g_cand_orig[f] = n;
                ((float4*)g_cand_box)[f] = make_float4(sm.x1[p], sm.y1[p], sm.x2[p], sm.y2[p]);
            }
        }
    }
    // publish completion
    __threadfence();
    __syncthreads();
    if (tid == 0) atomicAdd(&g_done, 1);
}

// ---------- topk block ----------
__device__ void run_topk(TopkView& sm, int tid, float* __restrict__ d_out) {
    if (tid == 0) {
        while (poll_int(&g_done) < NC2) __nanosleep(200);
    }
    __syncthreads();
    __threadfence();

    int P = g_pcnt;
    if (P > NC2 * NPROP) P = NC2 * NPROP;

    for (int i = tid; i < NBIN; i += 256) sm.hist[i] = 0;
    for (int i = tid; i < 2048; i += 256) sm.key[i] = 0ULL;
    if (tid == 0) { sm.B = 0; sm.cnt = 0; }
    __syncthreads();

    // pass 1: histogram of high score bits (bins cover (0.05, 1.0])
    for (int i = tid; i < P; i += 256) {
        unsigned sb = (unsigned)(g_plist[i] >> 32);
        int b = (int)(sb >> 16) - 0x3D40;
        b = b < 0 ? 0 : (b > NBIN - 1 ? NBIN - 1 : b);
        atomicAdd(&sm.hist[b], 1);
    }
    __syncthreads();

    // two-level inclusive-suffix scan: thread t owns bins [4t, 4t+3]
    int base = tid * 4;
    int h0 = sm.hist[base], h1 = sm.hist[base + 1], h2 = sm.hist[base + 2], h3 = sm.hist[base + 3];
    sm.part[tid] = h0 + h1 + h2 + h3;
    __syncthreads();
    for (int st = 1; st < 256; st <<= 1) {
        int v = sm.part[tid] + ((tid + st < 256) ? sm.part[tid + st] : 0);
        __syncthreads();
        sm.part[tid] = v;
        __syncthreads();
    }
    {
        int T = (tid < 255) ? sm.part[tid + 1] : 0;   // suffix over bins >= base+4
        int s3 = T + h3, s2 = s3 + h2, s1 = s2 + h1, s0 = s1 + h0;
        if (s0 >= KDET && s1 < KDET) sm.B = base;
        if (s1 >= KDET && s2 < KDET) sm.B = base + 1;
        if (s2 >= KDET && s3 < KDET) sm.B = base + 2;
        if (s3 >= KDET && T  < KDET) sm.B = base + 3;
    }
    __syncthreads();
    const int B = sm.B;

    // pass 2: collect candidates in bins >= B
    for (int i = tid; i < P; i += 256) {
        unsigned long long key = g_plist[i];
        int b = (int)((unsigned)(key >> 32) >> 16) - 0x3D40;
        b = b < 0 ? 0 : (b > NBIN - 1 ? NBIN - 1 : b);
        if (b >= B) {
            int p = atomicAdd(&sm.cnt, 1);
            if (p < 2048) sm.key[p] = key;
        }
    }
    __syncthreads();
    int cnt = sm.cnt;

    if (cnt <= 2048) {
        int Sp = 128; while (Sp < cnt) Sp <<= 1;
        bitonic_desc(sm.key, Sp, tid, 256);
    } else {
        // pathological tie overflow: exact chunked-carry over all candidates
        for (int i = tid; i < 2048; i += 256) sm.key[i] = (i < P) ? g_plist[i] : 0ULL;
        __syncthreads();
        bitonic_desc(sm.key, 2048, tid, 256);
        int pos = 2048;
        while (pos < P) {
            int c2 = P - pos; if (c2 > 1920) c2 = 1920;
            for (int i = tid; i < 1920; i += 256)
                sm.key[128 + i] = (i < c2) ? g_plist[pos + i] : 0ULL;
            __syncthreads();
            bitonic_desc(sm.key, 2048, tid, 256);
            pos += 1920;
        }
    }

    // outputs
    if (tid < KDET) {
        unsigned long long key = sm.key[tid];
        float sc = 0.0f; int label = 0; int orig = -1;
        float4 bx = make_float4(0.f, 0.f, 0.f, 0.f);
        if (key) {
            sc = __uint_as_float((unsigned)(key >> 32));
            int f = 0x7FFFFFFF - (int)(key & 0xFFFFFFFFULL);
            bx = ((const float4*)g_cand_box)[f];
            label = (f >> 10) + 1;
            orig = g_cand_orig[f];
        }
        d_out[tid * 4 + 0] = bx.x;
        d_out[tid * 4 + 1] = bx.y;
        d_out[tid * 4 + 2] = bx.z;
        d_out[tid * 4 + 3] = bx.w;
        d_out[KDET * 4 + tid] = sc;
        d_out[KDET * 4 + KDET + KDET * FDIM + tid] = (float)label;
        g_sel_orig[tid] = orig;
    }
    __threadfence();
    __syncthreads();
    if (tid == 0) atomicExch(&g_feat_flag, 1);
}

// ---------- feat block (128 working threads, MLP=2 per thread) ----------
__device__ void run_feat(int k, int tid,
                         const float* __restrict__ features, float* __restrict__ d_out) {
    if (tid == 0) {
        while (poll_int(&g_feat_flag) == 0) __nanosleep(200);
    }
    __syncthreads();
    __threadfence();
    int orig = g_sel_orig[k];
    float4* dst = (float4*)(d_out + KDET * 4 + KDET + (size_t)k * FDIM);
    if (tid < 128) {
        if (orig >= 0) {
            const float4* src = (const float4*)(features + (size_t)orig * FDIM);
            float4 a = __ldg(src + tid);
            float4 b = __ldg(src + tid + 128);
            dst[tid] = a; dst[tid + 128] = b;
        } else {
            dst[tid] = make_float4(0.f, 0.f, 0.f, 0.f);
            dst[tid + 128] = make_float4(0.f, 0.f, 0.f, 0.f);
        }
    }
    // last feat block resets all sync state for the next graph replay
    __threadfence();
    __syncthreads();
    if (tid == 0) {
        int v = atomicAdd(&g_feat_done, 1);
        if (v == KDET - 1) {
            g_pcnt = 0; g_stats_done = 0; g_done = 0; g_feat_flag = 0; g_feat_done = 0;
        }
    }
}

// ---------- single persistent mega-kernel ----------
__global__ void __launch_bounds__(256, 1)
mega_kernel(const float* __restrict__ logits,
            const float* __restrict__ box_reg,
            const float* __restrict__ proposals,
            const float* __restrict__ features,
            float* __restrict__ d_out) {
    __shared__ SMemU sm;
    const int bid = blockIdx.x, tid = threadIdx.x;
    if (bid < NC2) {
        run_rowstats_and_join(bid, tid, logits);
        run_class_nms(sm.nms, bid, tid, logits, box_reg, proposals);
    } else if (bid == NC2) {
        run_topk(sm.tk, tid, d_out);
    } else {
        run_feat(bid - NC2 - 1, tid, features, d_out);
    }
}

// ---------- launch ----------
extern "C" void kernel_launch(void* const* d_in, const int* in_sizes, int n_in,
                              void* d_out, int out_size) {
    const float* logits  = (const float*)d_in[0];   // [N, 81]
    const float* box_reg = (const float*)d_in[1];   // [N, 324]
    const float* props   = (const float*)d_in[2];   // [N, 4]
    const float* feats   = (const float*)d_in[3];   // [N, 1024]
    float* out = (float*)d_out;

    mega_kernel<<<NC2 + 1 + KDET, 256>>>(logits, box_reg, props, feats, out);
}

// round 8
// speedup vs baseline: 1.0483x; 1.0483x over previous
#include <cuda_runtime.h>

#define NPROP 1024
#define NCLS  81
#define NC2   80        // foreground classes
#define KDET  100
#define FDIM  1024
#define IMG_W 1216.0f
#define IMG_H 800.0f
#define SCORE_TH 0.05f
#define NMS_TH 0.5f
#define BBOX_CLIP 4.135166556742356f   // log(1000/16)

#define MMASK 256       // bitmask-NMS fast path capacity
#define WMASK 4         // 256/64 words
#define NBIN  1024

// ---------- device scratch (statically zero-initialized) ----------
__device__ float  g_probsT[NCLS * NPROP];            // [class][row] transposed probs
__device__ float  g_cand_box[NC2 * NPROP * 4];       // flat f = c*NPROP + sorted_pos
__device__ int    g_cand_orig[NC2 * NPROP];
__device__ unsigned long long g_plist[NC2 * NPROP];  // packed kept candidates
__device__ int    g_hist[NBIN];                      // global score histogram (emit-time)
__device__ int    g_pcnt;
__device__ int    g_feat_flag;
__device__ int    g_sel_orig[KDET];

__device__ __forceinline__ int poll_int(const int* p) {
    int v;
    asm volatile("ld.volatile.global.s32 %0, [%1];" : "=r"(v) : "l"(p));
    return v;
}
__device__ __forceinline__ int score_bin(unsigned sbits) {
    int b = (int)(sbits >> 16) - 0x3D40;
    return b < 0 ? 0 : (b > NBIN - 1 ? NBIN - 1 : b);
}

// ---------- K1: softmax probs (transposed) + state reset ----------
__global__ void probs_kernel(const float* __restrict__ logits) {
    if (blockIdx.x == 0) {
        if (threadIdx.x == 0) { g_pcnt = 0; g_feat_flag = 0; }
        for (int i = threadIdx.x; i < NBIN; i += 256) g_hist[i] = 0;
    }
    const int row  = blockIdx.x * 8 + (threadIdx.x >> 5);   // warp per row
    const int lane = threadIdx.x & 31;
    const float* lp = logits + (size_t)row * NCLS;
    float l0 = lp[lane];
    float l1 = lp[lane + 32];
    float l2 = (lane < NCLS - 64) ? lp[lane + 64] : -3.4e38f;
    float mx = fmaxf(fmaxf(l0, l1), l2);
    for (int o = 16; o; o >>= 1) mx = fmaxf(mx, __shfl_xor_sync(0xffffffffu, mx, o));
    float e0 = expf(l0 - mx);
    float e1 = expf(l1 - mx);
    float e2 = (lane < NCLS - 64) ? expf(l2 - mx) : 0.0f;
    float sum = e0 + e1 + e2;
    for (int o = 16; o; o >>= 1) sum += __shfl_xor_sync(0xffffffffu, sum, o);
    g_probsT[lane * NPROP + row]        = e0 / sum;
    g_probsT[(lane + 32) * NPROP + row] = e1 / sum;
    if (lane < NCLS - 64) g_probsT[(lane + 64) * NPROP + row] = e2 / sum;
}

// ---------- K2: per-class compact + sort + decode + bitmask NMS + emit ----------
__global__ void __launch_bounds__(256)
class_nms_kernel(const float* __restrict__ box_reg,
                 const float* __restrict__ proposals) {
    const int c = blockIdx.x;             // foreground class 0..79 (real class c+1)
    const int tid = threadIdx.x, bd = 256;
    const int lane = tid & 31;

    __shared__ int s_cnt;
    __shared__ unsigned long long s_key[NPROP];                  // 8 KB
    __shared__ float s_x1[NPROP], s_y1[NPROP], s_x2[NPROP], s_y2[NPROP], s_area[NPROP];
    __shared__ unsigned long long s_mask[MMASK * WMASK];         // 8 KB
    __shared__ unsigned long long s_kw[WMASK];
    __shared__ unsigned char s_keep[NPROP];                      // fallback

    if (tid == 0) s_cnt = 0;
    __syncthreads();

    // Phase A: coalesced read of this class's prob column; ballot-aggregated compact
    const float* pcol = g_probsT + (size_t)(c + 1) * NPROP;
    for (int n = tid; n < NPROP; n += bd) {
        float p = pcol[n];
        bool v = p > SCORE_TH;
        unsigned m = __ballot_sync(0xffffffffu, v);
        if (m) {
            int leader = __ffs(m) - 1;
            int base = 0;
            if (lane == leader) base = atomicAdd(&s_cnt, __popc(m));
            base = __shfl_sync(0xffffffffu, base, leader);
            if (v) {
                int pos = base + __popc(m & ((1u << lane) - 1));
                s_key[pos] = ((unsigned long long)__float_as_uint(p) << 32) |
                             (unsigned)(NPROP - 1 - n);   // lower n wins ties
            }
        }
    }
    __syncthreads();
    const int M = s_cnt;
    if (M == 0) return;
    int Mp = 1; while (Mp < M) Mp <<= 1;
    for (int p = M + tid; p < Mp; p += bd) s_key[p] = 0ULL;
    __syncthreads();

    // Phase B: bitonic sort descending
    if (M > 1) {
        for (int k = 2; k <= Mp; k <<= 1) {
            for (int j = k >> 1; j > 0; j >>= 1) {
                for (int i = tid; i < Mp; i += bd) {
                    int ixj = i ^ j;
                    if (ixj > i) {
                        unsigned long long a = s_key[i], b = s_key[ixj];
                        bool descBlock = ((i & k) == 0);
                        if (descBlock ? (a < b) : (a > b)) { s_key[i] = b; s_key[ixj] = a; }
                    }
                }
                __syncthreads();
            }
        }
    }

    // Phase C: decode + clip
    for (int p = tid; p < M; p += bd) {
        int n = (NPROP - 1) - (int)(s_key[p] & 0xFFFFFFFFULL);
        float4 pb = __ldg((const float4*)proposals + n);
        float w = pb.z - pb.x + 1.0f, h = pb.w - pb.y + 1.0f;
        float cx = pb.x + 0.5f * w,  cy = pb.y + 0.5f * h;
        float4 r = __ldg((const float4*)(box_reg + (size_t)n * (NCLS * 4) + (c + 1) * 4));
        float dx = r.x / 10.0f, dy = r.y / 10.0f;
        float dw = fminf(r.z / 5.0f, BBOX_CLIP);
        float dh = fminf(r.w / 5.0f, BBOX_CLIP);
        float pcx = dx * w + cx, pcy = dy * h + cy;
        float pw = expf(dw) * w, ph = expf(dh) * h;
        float x1 = pcx - 0.5f * pw, y1 = pcy - 0.5f * ph;
        float x2 = pcx + 0.5f * pw - 1.0f, y2 = pcy + 0.5f * ph - 1.0f;
        x1 = fminf(fmaxf(x1, 0.0f), IMG_W - 1.0f);
        y1 = fminf(fmaxf(y1, 0.0f), IMG_H - 1.0f);
        x2 = fminf(fmaxf(x2, 0.0f), IMG_W - 1.0f);
        y2 = fminf(fmaxf(y2, 0.0f), IMG_H - 1.0f);
        s_x1[p] = x1; s_y1[p] = y1; s_x2[p] = x2; s_y2[p] = y2;
        s_area[p] = (x2 - x1 + 1.0f) * (y2 - y1 + 1.0f);
        s_keep[p] = 1;
    }
    __syncthreads();

    const bool fastpath = (M <= MMASK);
    if (fastpath) {
        const int nwords = M * WMASK;
        for (int idx = tid; idx < nwords; idx += bd) {
            int i = idx >> 2, w = idx & 3;
            float xi1 = s_x1[i], yi1 = s_y1[i], xi2 = s_x2[i], yi2 = s_y2[i], ai = s_area[i];
            unsigned long long bits = 0ULL;
            int jlo = w << 6;
            int jhi = jlo + 64; if (jhi > M) jhi = M;
            int j0 = (i + 1 > jlo) ? i + 1 : jlo;
            for (int j = j0; j < jhi; j++) {
                float xx1 = fmaxf(xi1, s_x1[j]);
                float yy1 = fmaxf(yi1, s_y1[j]);
                float xx2 = fminf(xi2, s_x2[j]);
                float yy2 = fminf(yi2, s_y2[j]);
                float ww = fmaxf(xx2 - xx1 + 1.0f, 0.0f);
                float hh = fmaxf(yy2 - yy1 + 1.0f, 0.0f);
                float inter = ww * hh;
                float iou = inter / (ai + s_area[j] - inter);
                if (iou > NMS_TH) bits |= 1ULL << (j - jlo);
            }
            s_mask[idx] = bits;
        }
        __syncthreads();
        if (tid == 0) {
            unsigned long long kw0 = ~0ULL, kw1 = ~0ULL, kw2 = ~0ULL, kw3 = ~0ULL;
            for (int i = 0; i < M; i++) {
                unsigned long long ow = (i < 64) ? kw0 : (i < 128) ? kw1 : (i < 192) ? kw2 : kw3;
                if ((ow >> (i & 63)) & 1ULL) {
                    const unsigned long long* row = &s_mask[i << 2];
                    kw0 &= ~row[0]; kw1 &= ~row[1]; kw2 &= ~row[2]; kw3 &= ~row[3];
                }
            }
            s_kw[0] = kw0; s_kw[1] = kw1; s_kw[2] = kw2; s_kw[3] = kw3;
        }
        __syncthreads();
    } else {
        for (int i = 0; i < M; i++) {
            if (s_keep[i]) {
                float xi1 = s_x1[i], yi1 = s_y1[i], xi2 = s_x2[i], yi2 = s_y2[i], ai = s_area[i];
                for (int j = i + 1 + tid; j < M; j += bd) {
                    if (s_keep[j]) {
                        float xx1 = fmaxf(xi1, s_x1[j]);
                        float yy1 = fmaxf(yi1, s_y1[j]);
                        float xx2 = fminf(xi2, s_x2[j]);
                        float yy2 = fminf(yi2, s_y2[j]);
                        float ww = fmaxf(xx2 - xx1 + 1.0f, 0.0f);
                        float hh = fmaxf(yy2 - yy1 + 1.0f, 0.0f);
                        float inter = ww * hh;
                        float iou = inter / (ai + s_area[j] - inter);
                        if (iou > NMS_TH) s_keep[j] = 0;
                    }
                }
            }
            __syncthreads();
        }
    }

    // Phase E: emit kept candidates + global histogram
    for (int p = tid; p < M; p += bd) {
        bool kept = fastpath ? ((s_kw[p >> 6] >> (p & 63)) & 1ULL) : (bool)s_keep[p];
        if (kept) {
            int f = c * NPROP + p;
            unsigned long long key = s_key[p];
            unsigned sbits = (unsigned)(key >> 32);
            int n = (NPROP - 1) - (int)(key & 0xFFFFFFFFULL);
            int gp = atomicAdd(&g_pcnt, 1);
            g_plist[gp] = ((unsigned long long)sbits << 32) | (unsigned)(0x7FFFFFFF - f);
            atomicAdd(&g_hist[score_bin(sbits)], 1);
            g_cand_orig[f] = n;
            ((float4*)g_cand_box)[f] = make_float4(s_x1[p], s_y1[p], s_x2[p], s_y2[p]);
        }
    }
}

// ---------- bitonic sort (descending) ----------
__device__ __forceinline__ void bitonic_desc(unsigned long long* key, int Sp, int tid, int nthr) {
    for (int k = 2; k <= Sp; k <<= 1) {
        for (int j = k >> 1; j > 0; j >>= 1) {
            for (int i = tid; i < Sp; i += nthr) {
                int ixj = i ^ j;
                if (ixj > i) {
                    unsigned long long a = key[i], b = key[ixj];
                    bool descBlock = ((i & k) == 0);
                    if (descBlock ? (a < b) : (a > b)) { key[i] = b; key[ixj] = a; }
                }
            }
            __syncthreads();
        }
    }
}

// ---------- K3: fused top-K (block 0) + feature gather (blocks 1..100) ----------
__global__ void __launch_bounds__(256)
topk_feat_kernel(const float* __restrict__ features, float* __restrict__ d_out) {
    __shared__ int s_part[256];
    __shared__ unsigned long long s_key[2048];
    __shared__ int s_B, s_cnt;
    const int tid = threadIdx.x;

    if (blockIdx.x != 0) {
        // ---- feature gather block ----
        const int k = blockIdx.x - 1;
        if (tid == 0) {
            while (poll_int(&g_feat_flag) == 0) __nanosleep(100);
        }
        __syncthreads();
        __threadfence();
        int orig = g_sel_orig[k];
        float4* dst = (float4*)(d_out + KDET * 4 + KDET + (size_t)k * FDIM);
        if (tid < 128) {
            if (orig >= 0) {
                const float4* src = (const float4*)(features + (size_t)orig * FDIM);
                float4 a = __ldg(src + tid);
                float4 b = __ldg(src + tid + 128);
                dst[tid] = a; dst[tid + 128] = b;
            } else {
                dst[tid] = make_float4(0.f, 0.f, 0.f, 0.f);
                dst[tid + 128] = make_float4(0.f, 0.f, 0.f, 0.f);
            }
        }
        return;
    }

    // ---- top-K block ----
    int P = g_pcnt;
    if (P > NC2 * NPROP) P = NC2 * NPROP;

    for (int i = tid; i < 2048; i += 256) s_key[i] = 0ULL;
    if (tid == 0) { s_B = 0; s_cnt = 0; }

    // suffix-scan of the global histogram (built by K2)
    int base = tid * 4;
    int h0 = g_hist[base], h1 = g_hist[base + 1], h2 = g_hist[base + 2], h3 = g_hist[base + 3];
    s_part[tid] = h0 + h1 + h2 + h3;
    __syncthreads();
    for (int st = 1; st < 256; st <<= 1) {
        int v = s_part[tid] + ((tid + st < 256) ? s_part[tid + st] : 0);
        __syncthreads();
        s_part[tid] = v;
        __syncthreads();
    }
    {
        int T = (tid < 255) ? s_part[tid + 1] : 0;
        int s3 = T + h3, s2 = s3 + h2, s1 = s2 + h1, s0 = s1 + h0;
        if (s0 >= KDET && s1 < KDET) s_B = base;
        if (s1 >= KDET && s2 < KDET) s_B = base + 1;
        if (s2 >= KDET && s3 < KDET) s_B = base + 2;
        if (s3 >= KDET && T  < KDET) s_B = base + 3;
    }
    __syncthreads();
    const int B = s_B;

    // collect candidates in bins >= B
    for (int i = tid; i < P; i += 256) {
        unsigned long long key = g_plist[i];
        if (score_bin((unsigned)(key >> 32)) >= B) {
            int p = atomicAdd(&s_cnt, 1);
            if (p < 2048) s_key[p] = key;
        }
    }
    __syncthreads();
    int cnt = s_cnt;

    if (cnt <= 2048) {
        int Sp = 128; while (Sp < cnt) Sp <<= 1;
        bitonic_desc(s_key, Sp, tid, 256);
    } else {
        // pathological tie overflow: exact chunked-carry over all candidates
        for (int i = tid; i < 2048; i += 256) s_key[i] = (i < P) ? g_plist[i] : 0ULL;
        __syncthreads();
        bitonic_desc(s_key, 2048, tid, 256);
        int pos = 2048;
        while (pos < P) {
            int c2 = P - pos; if (c2 > 1920) c2 = 1920;
            for (int i = tid; i < 1920; i += 256)
                s_key[128 + i] = (i < c2) ? g_plist[pos + i] : 0ULL;
            __syncthreads();
            bitonic_desc(s_key, 2048, tid, 256);
            pos += 1920;
        }
    }

    // publish selection FIRST so feat blocks start, then write boxes/scores/labels
    unsigned long long key = 0ULL;
    float sc = 0.0f; int label = 0; int orig = -1;
    float4 bx = make_float4(0.f, 0.f, 0.f, 0.f);
    if (tid < KDET) {
        key = s_key[tid];
        if (key) {
            sc = __uint_as_float((unsigned)(key >> 32));
            int f = 0x7FFFFFFF - (int)(key & 0xFFFFFFFFULL);
            bx = ((const float4*)g_cand_box)[f];
            label = (f >> 10) + 1;
            orig = g_cand_orig[f];
        }
        g_sel_orig[tid] = orig;
    }
    __threadfence();
    __syncthreads();
    if (tid == 0) atomicExch(&g_feat_flag, 1);

    if (tid < KDET) {
        d_out[tid * 4 + 0] = bx.x;
        d_out[tid * 4 + 1] = bx.y;
        d_out[tid * 4 + 2] = bx.z;
        d_out[tid * 4 + 3] = bx.w;
        d_out[KDET * 4 + tid] = sc;
        d_out[KDET * 4 + KDET + KDET * FDIM + tid] = (float)label;
    }
}

// ---------- launch ----------
extern "C" void kernel_launch(void* const* d_in, const int* in_sizes, int n_in,
                              void* d_out, int out_size) {
    const float* logits  = (const float*)d_in[0];   // [N, 81]
    const float* box_reg = (const float*)d_in[1];   // [N, 324]
    const float* props   = (const float*)d_in[2];   // [N, 4]
    const float* feats   = (const float*)d_in[3];   // [N, 1024]
    float* out = (float*)d_out;

    probs_kernel<<<NPROP / 8, 256>>>(logits);
    class_nms_kernel<<<NC2, 256>>>(box_reg, props);
    topk_feat_kernel<<<1 + KDET, 256>>>(feats, out);
}

// round 10
// speedup vs baseline: 1.2002x; 1.1449x over previous
#include <cuda_runtime.h>

#define NPROP 1024
#define NCLS  81
#define NC2   80        // foreground classes
#define KDET  100
#define FDIM  1024
#define IMG_W 1216.0f
#define IMG_H 800.0f
#define SCORE_TH 0.05f
#define NMS_TH 0.5f
#define BBOX_CLIP 4.135166556742356f   // log(1000/16)

#define MMASK 256       // bitmask-NMS / rank-sort fast path capacity
#define WMASK 4         // 256/64 words
#define NBIN  1024

// ---------- device scratch (statically zero-initialized) ----------
__device__ float  g_probsT[NCLS * NPROP];            // [class][row] transposed probs
__device__ float  g_cand_box[NC2 * NPROP * 4];       // flat f = c*NPROP + sorted_pos
__device__ int    g_cand_orig[NC2 * NPROP];
__device__ unsigned long long g_plist[NC2 * NPROP];  // packed kept candidates
__device__ int    g_hist[NBIN];                      // global score histogram (emit-time)
__device__ int    g_pcnt;
__device__ int    g_done;        // class blocks completed
__device__ int    g_feat_flag;   // selection published
__device__ int    g_sel_orig[KDET];

__device__ __forceinline__ int poll_int(const int* p) {
    int v;
    asm volatile("ld.volatile.global.s32 %0, [%1];" : "=r"(v) : "l"(p));
    return v;
}
__device__ __forceinline__ int score_bin(unsigned sbits) {
    int b = (int)(sbits >> 16) - 0x3D40;
    return b < 0 ? 0 : (b > NBIN - 1 ? NBIN - 1 : b);
}

// ---------- K1: softmax probs (transposed) + state reset ----------
__global__ void probs_kernel(const float* __restrict__ logits) {
    if (blockIdx.x == 0) {
        if (threadIdx.x == 0) { g_pcnt = 0; g_done = 0; g_feat_flag = 0; }
        for (int i = threadIdx.x; i < NBIN; i += 256) g_hist[i] = 0;
    }
    const int row  = blockIdx.x * 8 + (threadIdx.x >> 5);   // warp per row
    const int lane = threadIdx.x & 31;
    const float* lp = logits + (size_t)row * NCLS;
    float l0 = lp[lane];
    float l1 = lp[lane + 32];
    float l2 = (lane < NCLS - 64) ? lp[lane + 64] : -3.4e38f;
    float mx = fmaxf(fmaxf(l0, l1), l2);
    for (int o = 16; o; o >>= 1) mx = fmaxf(mx, __shfl_xor_sync(0xffffffffu, mx, o));
    float e0 = expf(l0 - mx);
    float e1 = expf(l1 - mx);
    float e2 = (lane < NCLS - 64) ? expf(l2 - mx) : 0.0f;
    float sum = e0 + e1 + e2;
    for (int o = 16; o; o >>= 1) sum += __shfl_xor_sync(0xffffffffu, sum, o);
    g_probsT[lane * NPROP + row]        = e0 / sum;
    g_probsT[(lane + 32) * NPROP + row] = e1 / sum;
    if (lane < NCLS - 64) g_probsT[(lane + 64) * NPROP + row] = e2 / sum;
}

// ---------- shared memory union ----------
struct NmsView {
    unsigned long long key[NPROP];           // 8 KB (also rank-sorted keys)
    float x1[NPROP], y1[NPROP], x2[NPROP], y2[NPROP], area[NPROP]; // 20 KB
    unsigned long long mask[MMASK * WMASK];  // 8 KB (also temp sorted-key buffer)
    unsigned long long kw[WMASK];
    unsigned char keep[NPROP];               // fallback
    int cnt;
};
struct TopkView {
    int part[256];                           // 1 KB
    unsigned long long key[2048];            // 16 KB
    unsigned long long top[KDET + 28];       // 1 KB
    int B, cnt;
};
union SMemU { NmsView nms; TopkView tk; };

// ---------- bitonic sort (descending) — fallback only ----------
__device__ __forceinline__ void bitonic_desc(unsigned long long* key, int Sp, int tid, int nthr) {
    for (int k = 2; k <= Sp; k <<= 1) {
        for (int j = k >> 1; j > 0; j >>= 1) {
            for (int i = tid; i < Sp; i += nthr) {
                int ixj = i ^ j;
                if (ixj > i) {
                    unsigned long long a = key[i], b = key[ixj];
                    bool descBlock = ((i & k) == 0);
                    if (descBlock ? (a < b) : (a > b)) { key[i] = b; key[ixj] = a; }
                }
            }
            __syncthreads();
        }
    }
}

// ---------- decode one box into sorted slot r ----------
__device__ __forceinline__ void decode_box(NmsView& sm, int r, unsigned long long key, int c,
                                           const float* __restrict__ box_reg,
                                           const float* __restrict__ proposals) {
    int n = (NPROP - 1) - (int)(key & 0xFFFFFFFFULL);
    float4 pb = __ldg((const float4*)proposals + n);
    float w = pb.z - pb.x + 1.0f, h = pb.w - pb.y + 1.0f;
    float cx = pb.x + 0.5f * w,  cy = pb.y + 0.5f * h;
    float4 rr = __ldg((const float4*)(box_reg + (size_t)n * (NCLS * 4) + (c + 1) * 4));
    float dx = rr.x / 10.0f, dy = rr.y / 10.0f;
    float dw = fminf(rr.z / 5.0f, BBOX_CLIP);
    float dh = fminf(rr.w / 5.0f, BBOX_CLIP);
    float pcx = dx * w + cx, pcy = dy * h + cy;
    float pw = expf(dw) * w, ph = expf(dh) * h;
    float x1 = pcx - 0.5f * pw, y1 = pcy - 0.5f * ph;
    float x2 = pcx + 0.5f * pw - 1.0f, y2 = pcy + 0.5f * ph - 1.0f;
    x1 = fminf(fmaxf(x1, 0.0f), IMG_W - 1.0f);
    y1 = fminf(fmaxf(y1, 0.0f), IMG_H - 1.0f);
    x2 = fminf(fmaxf(x2, 0.0f), IMG_W - 1.0f);
    y2 = fminf(fmaxf(y2, 0.0f), IMG_H - 1.0f);
    sm.x1[r] = x1; sm.y1[r] = y1; sm.x2[r] = x2; sm.y2[r] = y2;
    sm.area[r] = (x2 - x1 + 1.0f) * (y2 - y1 + 1.0f);
    sm.keep[r] = 1;
}

// ---------- class block: compact + rank-order + decode + bitmask NMS + emit ----------
__device__ void run_class_nms(NmsView& sm, int c, int tid,
                              const float* __restrict__ box_reg,
                              const float* __restrict__ proposals) {
    const int bd = 256;
    const int lane = tid & 31;
    if (tid == 0) sm.cnt = 0;
    __syncthreads();

    // Phase A: coalesced read of prob column; ballot-aggregated compact
    const float* pcol = g_probsT + (size_t)(c + 1) * NPROP;
    for (int n = tid; n < NPROP; n += bd) {
        float p = pcol[n];
        bool v = p > SCORE_TH;
        unsigned m = __ballot_sync(0xffffffffu, v);
        if (m) {
            int leader = __ffs(m) - 1;
            int base = 0;
            if (lane == leader) base = atomicAdd(&sm.cnt, __popc(m));
            base = __shfl_sync(0xffffffffu, base, leader);
            if (v) {
                int pos = base + __popc(m & ((1u << lane) - 1));
                sm.key[pos] = ((unsigned long long)__float_as_uint(p) << 32) |
                              (unsigned)(NPROP - 1 - n);   // lower n wins ties
            }
        }
    }
    __syncthreads();
    const int M = sm.cnt;
    if (M == 0) {
        if (tid == 0) { __threadfence(); atomicAdd(&g_done, 1); }
        return;
    }

    const bool fastpath = (M <= MMASK);
    if (fastpath) {
        // Rank-order: sorted position = #{keys greater}. 2 barriers, no bitonic.
        if (tid < M) {
            unsigned long long k = sm.key[tid];
            int r = 0;
            for (int j = 0; j < M; j++) r += (sm.key[j] > k);
            sm.mask[r] = k;                       // temp sorted-key buffer
            decode_box(sm, r, k, c, box_reg, proposals);
        }
        __syncthreads();
        if (tid < M) sm.key[tid] = sm.mask[tid];  // keys now sorted descending
        __syncthreads();

        // parallel suppression bitmask
        const int nwords = M * WMASK;
        for (int idx = tid; idx < nwords; idx += bd) {
            int i = idx >> 2, w = idx & 3;
            float xi1 = sm.x1[i], yi1 = sm.y1[i], xi2 = sm.x2[i], yi2 = sm.y2[i], ai = sm.area[i];
            unsigned long long bits = 0ULL;
            int jlo = w << 6;
            int jhi = jlo + 64; if (jhi > M) jhi = M;
            int j0 = (i + 1 > jlo) ? i + 1 : jlo;
            for (int j = j0; j < jhi; j++) {
                float xx1 = fmaxf(xi1, sm.x1[j]);
                float yy1 = fmaxf(yi1, sm.y1[j]);
                float xx2 = fminf(xi2, sm.x2[j]);
                float yy2 = fminf(yi2, sm.y2[j]);
                float ww = fmaxf(xx2 - xx1 + 1.0f, 0.0f);
                float hh = fmaxf(yy2 - yy1 + 1.0f, 0.0f);
                float inter = ww * hh;
                float iou = inter / (ai + sm.area[j] - inter);
                if (iou > NMS_TH) bits |= 1ULL << (j - jlo);
            }
            sm.mask[idx] = bits;
        }
        __syncthreads();
        if (tid == 0) {
            unsigned long long kw0 = ~0ULL, kw1 = ~0ULL, kw2 = ~0ULL, kw3 = ~0ULL;
            for (int i = 0; i < M; i++) {
                unsigned long long ow = (i < 64) ? kw0 : (i < 128) ? kw1 : (i < 192) ? kw2 : kw3;
                if ((ow >> (i & 63)) & 1ULL) {
                    const unsigned long long* row = &sm.mask[i << 2];
                    kw0 &= ~row[0]; kw1 &= ~row[1]; kw2 &= ~row[2]; kw3 &= ~row[3];
                }
            }
            sm.kw[0] = kw0; sm.kw[1] = kw1; sm.kw[2] = kw2; sm.kw[3] = kw3;
        }
        __syncthreads();
    } else {
        // fallback: bitonic sort + barrier NMS (statistically rare)
        int Mp = 1; while (Mp < M) Mp <<= 1;
        for (int p = M + tid; p < Mp; p += bd) sm.key[p] = 0ULL;
        __syncthreads();
        bitonic_desc(sm.key, Mp, tid, bd);
        for (int p = tid; p < M; p += bd)
            decode_box(sm, p, sm.key[p], c, box_reg, proposals);
        __syncthreads();
        for (int i = 0; i < M; i++) {
            if (sm.keep[i]) {
                float xi1 = sm.x1[i], yi1 = sm.y1[i], xi2 = sm.x2[i], yi2 = sm.y2[i], ai = sm.area[i];
                for (int j = i + 1 + tid; j < M; j += bd) {
                    if (sm.keep[j]) {
                        float xx1 = fmaxf(xi1, sm.x1[j]);
                        float yy1 = fmaxf(yi1, sm.y1[j]);
                        float xx2 = fminf(xi2, sm.x2[j]);
                        float yy2 = fminf(yi2, sm.y2[j]);
                        float ww = fmaxf(xx2 - xx1 + 1.0f, 0.0f);
                        float hh = fmaxf(yy2 - yy1 + 1.0f, 0.0f);
                        float inter = ww * hh;
                        float iou = inter / (ai + sm.area[j] - inter);
                        if (iou > NMS_TH) sm.keep[j] = 0;
                    }
                }
            }
            __syncthreads();
        }
    }

    // emit kept candidates + global histogram
    for (int p = tid; p < M; p += bd) {
        bool kept = fastpath ? ((sm.kw[p >> 6] >> (p & 63)) & 1ULL) : (bool)sm.keep[p];
        if (kept) {
            int f = c * NPROP + p;
            unsigned long long key = sm.key[p];
            unsigned sbits = (unsigned)(key >> 32);
            int n = (NPROP - 1) - (int)(key & 0xFFFFFFFFULL);
            int gp = atomicAdd(&g_pcnt, 1);
            g_plist[gp] = ((unsigned long long)sbits << 32) | (unsigned)(0x7FFFFFFF - f);
            atomicAdd(&g_hist[score_bin(sbits)], 1);
            g_cand_orig[f] = n;
            ((float4*)g_cand_box)[f] = make_float4(sm.x1[p], sm.y1[p], sm.x2[p], sm.y2[p]);
        }
    }
    __threadfence();
    __syncthreads();
    if (tid == 0) atomicAdd(&g_done, 1);
}

// ---------- topk block ----------
__device__ void run_topk(TopkView& sm, int tid, float* __restrict__ d_out) {
    if (tid == 0) {
        while (poll_int(&g_done) < NC2) __nanosleep(100);
    }
    __syncthreads();
    __threadfence();

    int P = g_pcnt;
    if (P > NC2 * NPROP) P = NC2 * NPROP;

    if (tid < KDET) sm.top[tid] = 0ULL;
    if (tid == 0) { sm.B = 0; sm.cnt = 0; }

    // suffix-scan of global histogram
    int base = tid * 4;
    int h0 = g_hist[base], h1 = g_hist[base + 1], h2 = g_hist[base + 2], h3 = g_hist[base + 3];
    sm.part[tid] = h0 + h1 + h2 + h3;
    __syncthreads();
    for (int st = 1; st < 256; st <<= 1) {
        int v = sm.part[tid] + ((tid + st < 256) ? sm.part[tid + st] : 0);
        __syncthreads();
        sm.part[tid] = v;
        __syncthreads();
    }
    {
        int T = (tid < 255) ? sm.part[tid + 1] : 0;
        int s3 = T + h3, s2 = s3 + h2, s1 = s2 + h1, s0 = s1 + h0;
        if (s0 >= KDET && s1 < KDET) sm.B = base;
        if (s1 >= KDET && s2 < KDET) sm.B = base + 1;
        if (s2 >= KDET && s3 < KDET) sm.B = base + 2;
        if (s3 >= KDET && T  < KDET) sm.B = base + 3;
    }
    __syncthreads();
    const int B = sm.B;

    // collect candidates in bins >= B
    for (int i = tid; i < P; i += 256) {
        unsigned long long key = g_plist[i];
        if (score_bin((unsigned)(key >> 32)) >= B) {
            int pos = atomicAdd(&sm.cnt, 1);
            if (pos < 2048) sm.key[pos] = key;
        }
    }
    __syncthreads();
    int cnt = sm.cnt;

    if (cnt <= 512) {
        // rank-order the survivors; only ranks < KDET are outputs
        for (int i = tid; i < cnt; i += 256) {
            unsigned long long k = sm.key[i];
            int r = 0;
            for (int j = 0; j < cnt; j++) r += (sm.key[j] > k);
            if (r < KDET) sm.top[r] = k;
        }
        __syncthreads();
    } else if (cnt <= 2048) {
        int Sp = 128; while (Sp < cnt) Sp <<= 1;
        for (int i = cnt + tid; i < Sp; i += 256) sm.key[i] = 0ULL;
        __syncthreads();
        bitonic_desc(sm.key, Sp, tid, 256);
        if (tid < KDET) sm.top[tid] = sm.key[tid];
        __syncthreads();
    } else {
        // pathological tie overflow: exact chunked-carry over all candidates
        for (int i = tid; i < 2048; i += 256) sm.key[i] = (i < P) ? g_plist[i] : 0ULL;
        __syncthreads();
        bitonic_desc(sm.key, 2048, tid, 256);
        int pos = 2048;
        while (pos < P) {
            int c2 = P - pos; if (c2 > 1920) c2 = 1920;
            for (int i = tid; i < 1920; i += 256)
                sm.key[128 + i] = (i < c2) ? g_plist[pos + i] : 0ULL;
            __syncthreads();
            bitonic_desc(sm.key, 2048, tid, 256);
            pos += 1920;
        }
        if (tid < KDET) sm.top[tid] = sm.key[tid];
        __syncthreads();
    }

    // publish selection FIRST so feat blocks start, then write outputs
    unsigned long long key = 0ULL;
    float sc = 0.0f; int label = 0; int orig = -1;
    float4 bx = make_float4(0.f, 0.f, 0.f, 0.f);
    if (tid < KDET) {
        key = sm.top[tid];
        if (key) {
            sc = __uint_as_float((unsigned)(key >> 32));
            int f = 0x7FFFFFFF - (int)(key & 0xFFFFFFFFULL);
            bx = ((const float4*)g_cand_box)[f];
            label = (f >> 10) + 1;
            orig = g_cand_orig[f];
        }
        g_sel_orig[tid] = orig;
    }
    __threadfence();
    __syncthreads();
    if (tid == 0) atomicExch(&g_feat_flag, 1);

    if (tid < KDET) {
        d_out[tid * 4 + 0] = bx.x;
        d_out[tid * 4 + 1] = bx.y;
        d_out[tid * 4 + 2] = bx.z;
        d_out[tid * 4 + 3] = bx.w;
        d_out[KDET * 4 + tid] = sc;
        d_out[KDET * 4 + KDET + KDET * FDIM + tid] = (float)label;
    }
}

// ---------- feat block ----------
__device__ void run_feat(int k, int tid,
                         const float* __restrict__ features, float* __restrict__ d_out) {
    if (tid == 0) {
        while (poll_int(&g_feat_flag) == 0) __nanosleep(100);
    }
    __syncthreads();
    __threadfence();
    int orig = g_sel_orig[k];
    float4* dst = (float4*)(d_out + KDET * 4 + KDET + (size_t)k * FDIM);
    if (tid < 128) {
        if (orig >= 0) {
            const float4* src = (const float4*)(features + (size_t)orig * FDIM);
            float4 a = __ldg(src + tid);
            float4 b = __ldg(src + tid + 128);
            dst[tid] = a; dst[tid + 128] = b;
        } else {
            dst[tid] = make_float4(0.f, 0.f, 0.f, 0.f);
            dst[tid + 128] = make_float4(0.f, 0.f, 0.f, 0.f);
        }
    }
}

// ---------- K2: fused class-NMS + top-K + feature gather ----------
__global__ void __launch_bounds__(256, 1)
fused_kernel(const float* __restrict__ box_reg,
             const float* __restrict__ proposals,
             const float* __restrict__ features,
             float* __restrict__ d_out) {
    __shared__ SMemU sm;
    const int bid = blockIdx.x, tid = threadIdx.x;
    if (bid < NC2) {
        run_class_nms(sm.nms, bid, tid, box_reg, proposals);
    } else if (bid == NC2) {
        run_topk(sm.tk, tid, d_out);
    } else {
        run_feat(bid - NC2 - 1, tid, features, d_out);
    }
}

// ---------- launch ----------
extern "C" void kernel_launch(void* const* d_in, const int* in_sizes, int n_in,
                              void* d_out, int out_size) {
    const float* logits  = (const float*)d_in[0];   // [N, 81]
    const float* box_reg = (const float*)d_in[1];   // [N, 324]
    const float* props   = (const float*)d_in[2];   // [N, 4]
    const float* feats   = (const float*)d_in[3];   // [N, 1024]
    float* out = (float*)d_out;

    probs_kernel<<<NPROP / 8, 256>>>(logits);
    fused_kernel<<<NC2 + 1 + KDET, 256>>>(box_reg, props, feats, out);
}

// round 16
// speedup vs baseline: 1.2393x; 1.0326x over previous
#include <cuda_runtime.h>

#define NPROP 1024
#define NCLS  81
#define NC2   80        // foreground classes
#define KDET  100
#define FDIM  1024
#define IMG_W 1216.0f
#define IMG_H 800.0f
#define SCORE_TH 0.05f
#define NMS_TH 0.5f
#define BBOX_CLIP 4.135166556742356f   // log(1000/16)

#define MMASK 256       // bitmask-NMS / rank-sort fast path capacity
#define WMASK 4         // 256/64 words
#define NBIN  1024
#define NTHR  512
#define NSTAT 64        // blocks participating in rowstats (64 * 16 warps = 1024 rows)

// ---------- device scratch (statically zero-initialized) ----------
__device__ float  g_probsT[NCLS * NPROP];            // [class][row] transposed probs
__device__ float  g_cand_box[NC2 * NPROP * 4];       // flat f = c*NPROP + sorted_pos
__device__ int    g_cand_orig[NC2 * NPROP];
__device__ unsigned long long g_plist[NC2 * NPROP];  // packed kept candidates
__device__ int    g_hist[NBIN];                      // global score histogram
__device__ int    g_pcnt;
__device__ int    g_stats_done;  // rowstats blocks completed
__device__ int    g_done;        // class blocks completed
__device__ int    g_feat_flag;   // selection published
__device__ int    g_exit;        // blocks exited (for end-of-run reset)
__device__ int    g_sel_orig[KDET];

__device__ __forceinline__ int poll_int(const int* p) {
    int v;
    asm volatile("ld.volatile.global.s32 %0, [%1];" : "=r"(v) : "l"(p));
    return v;
}
__device__ __forceinline__ int score_bin(unsigned sbits) {
    int b = (int)(sbits >> 16) - 0x3D40;
    return b < 0 ? 0 : (b > NBIN - 1 ? NBIN - 1 : b);
}

// ---------- shared memory union ----------
struct NmsView {
    unsigned long long key[NPROP];           // 8 KB (also rank-sorted keys)
    float x1[NPROP], y1[NPROP], x2[NPROP], y2[NPROP], area[NPROP]; // 20 KB
    unsigned long long mask[MMASK * WMASK];  // 8 KB (also temp sorted-key buffer)
    unsigned long long kw[WMASK];
    unsigned char keep[NPROP];               // fallback
    int cnt;
};
struct TopkView {
    int part[256];                           // 1 KB
    unsigned long long key[2048];            // 16 KB
    unsigned long long top[KDET + 28];       // 1 KB
    int B, cnt;
};
union SMemU { NmsView nms; TopkView tk; };

// ---------- bitonic sort (descending) — fallback only ----------
__device__ __forceinline__ void bitonic_desc(unsigned long long* key, int Sp, int tid, int nthr) {
    for (int k = 2; k <= Sp; k <<= 1) {
        for (int j = k >> 1; j > 0; j >>= 1) {
            for (int i = tid; i < Sp; i += nthr) {
                int ixj = i ^ j;
                if (ixj > i) {
                    unsigned long long a = key[i], b = key[ixj];
                    bool descBlock = ((i & k) == 0);
                    if (descBlock ? (a < b) : (a > b)) { key[i] = b; key[ixj] = a; }
                }
            }
            __syncthreads();
        }
    }
}

// ---------- decode one box into sorted slot r ----------
__device__ __forceinline__ void decode_box(NmsView& sm, int r, unsigned long long key, int c,
                                           const float* __restrict__ box_reg,
                                           const float* __restrict__ proposals) {
    int n = (NPROP - 1) - (int)(key & 0xFFFFFFFFULL);
    float4 pb = __ldg((const float4*)proposals + n);
    float w = pb.z - pb.x + 1.0f, h = pb.w - pb.y + 1.0f;
    float cx = pb.x + 0.5f * w,  cy = pb.y + 0.5f * h;
    float4 rr = __ldg((const float4*)(box_reg + (size_t)n * (NCLS * 4) + (c + 1) * 4));
    float dx = rr.x / 10.0f, dy = rr.y / 10.0f;
    float dw = fminf(rr.z / 5.0f, BBOX_CLIP);
    float dh = fminf(rr.w / 5.0f, BBOX_CLIP);
    float pcx = dx * w + cx, pcy = dy * h + cy;
    float pw = expf(dw) * w, ph = expf(dh) * h;
    float x1 = pcx - 0.5f * pw, y1 = pcy - 0.5f * ph;
    float x2 = pcx + 0.5f * pw - 1.0f, y2 = pcy + 0.5f * ph - 1.0f;
    x1 = fminf(fmaxf(x1, 0.0f), IMG_W - 1.0f);
    y1 = fminf(fmaxf(y1, 0.0f), IMG_H - 1.0f);
    x2 = fminf(fmaxf(x2, 0.0f), IMG_W - 1.0f);
    y2 = fminf(fmaxf(y2, 0.0f), IMG_H - 1.0f);
    sm.x1[r] = x1; sm.y1[r] = y1; sm.x2[r] = x2; sm.y2[r] = y2;
    sm.area[r] = (x2 - x1 + 1.0f) * (y2 - y1 + 1.0f);
    sm.keep[r] = 1;
}

// ---------- class block ----------
__device__ void run_class_nms(NmsView& sm, int c, int tid,
                              const float* __restrict__ box_reg,
                              const float* __restrict__ proposals) {
    const int bd = NTHR;
    const int lane = tid & 31;

    // join on rowstats
    if (tid == 0) {
        while (poll_int(&g_stats_done) < NSTAT) __nanosleep(60);
        sm.cnt = 0;
    }
    __syncthreads();
    __threadfence();

    // Phase A: coalesced prob column read; ballot-aggregated compact
    const float* pcol = g_probsT + (size_t)(c + 1) * NPROP;
    for (int n = tid; n < NPROP; n += bd) {
        float p = pcol[n];
        bool v = p > SCORE_TH;
        unsigned m = __ballot_sync(0xffffffffu, v);
        if (m) {
            int leader = __ffs(m) - 1;
            int base = 0;
            if (lane == leader) base = atomicAdd(&sm.cnt, __popc(m));
            base = __shfl_sync(0xffffffffu, base, leader);
            if (v) {
                int pos = base + __popc(m & ((1u << lane) - 1));
                sm.key[pos] = ((unsigned long long)__float_as_uint(p) << 32) |
                              (unsigned)(NPROP - 1 - n);   // lower n wins ties
            }
        }
    }
    __syncthreads();
    const int M = sm.cnt;

    if (M > 0) {
        const bool fastpath = (M <= MMASK);
        if (fastpath) {
            // Rank-order: sorted position = #{keys greater}. 2 barriers.
            if (tid < M) {
                unsigned long long k = sm.key[tid];
                int r = 0;
                for (int j = 0; j < M; j++) r += (sm.key[j] > k);
                sm.mask[r] = k;
                decode_box(sm, r, k, c, box_reg, proposals);
            }
            __syncthreads();
            if (tid < M) sm.key[tid] = sm.mask[tid];
            __syncthreads();

            // parallel suppression bitmask
            const int nwords = M * WMASK;
            for (int idx = tid; idx < nwords; idx += bd) {
                int i = idx >> 2, w = idx & 3;
                float xi1 = sm.x1[i], yi1 = sm.y1[i], xi2 = sm.x2[i], yi2 = sm.y2[i], ai = sm.area[i];
                unsigned long long bits = 0ULL;
                int jlo = w << 6;
                int jhi = jlo + 64; if (jhi > M) jhi = M;
                int j0 = (i + 1 > jlo) ? i + 1 : jlo;
                for (int j = j0; j < jhi; j++) {
                    float xx1 = fmaxf(xi1, sm.x1[j]);
                    float yy1 = fmaxf(yi1, sm.y1[j]);
                    float xx2 = fminf(xi2, sm.x2[j]);
                    float yy2 = fminf(yi2, sm.y2[j]);
                    float ww = fmaxf(xx2 - xx1 + 1.0f, 0.0f);
                    float hh = fmaxf(yy2 - yy1 + 1.0f, 0.0f);
                    float inter = ww * hh;
                    float iou = inter / (ai + sm.area[j] - inter);
                    if (iou > NMS_TH) bits |= 1ULL << (j - jlo);
                }
                sm.mask[idx] = bits;
            }
            __syncthreads();
            // single-thread bit reduce, loads speculatively prefetched off the chain
            if (tid == 0) {
                unsigned long long kw0 = ~0ULL, kw1 = ~0ULL, kw2 = ~0ULL, kw3 = ~0ULL;
                for (int i = 0; i < M; i++) {
                    unsigned long long r0 = sm.mask[(i << 2) + 0];
                    unsigned long long r1 = sm.mask[(i << 2) + 1];
                    unsigned long long r2 = sm.mask[(i << 2) + 2];
                    unsigned long long r3 = sm.mask[(i << 2) + 3];
                    unsigned long long ow = (i < 64) ? kw0 : (i < 128) ? kw1 : (i < 192) ? kw2 : kw3;
                    if ((ow >> (i & 63)) & 1ULL) {
                        kw0 &= ~r0; kw1 &= ~r1; kw2 &= ~r2; kw3 &= ~r3;
                    }
                }
                sm.kw[0] = kw0; sm.kw[1] = kw1; sm.kw[2] = kw2; sm.kw[3] = kw3;
            }
            __syncthreads();
        } else {
            // fallback: bitonic + barrier NMS (statistically rare)
            int Mp = 1; while (Mp < M) Mp <<= 1;
            for (int p = M + tid; p < Mp; p += bd) sm.key[p] = 0ULL;
            __syncthreads();
            bitonic_desc(sm.key, Mp, tid, bd);
            for (int p = tid; p < M; p += bd)
                decode_box(sm, p, sm.key[p], c, box_reg, proposals);
            __syncthreads();
            for (int i = 0; i < M; i++) {
                if (sm.keep[i]) {
                    float xi1 = sm.x1[i], yi1 = sm.y1[i], xi2 = sm.x2[i], yi2 = sm.y2[i], ai = sm.area[i];
                    for (int j = i + 1 + tid; j < M; j += bd) {
                        if (sm.keep[j]) {
                            float xx1 = fmaxf(xi1, sm.x1[j]);
                            float yy1 = fmaxf(yi1, sm.y1[j]);
                            float xx2 = fminf(xi2, sm.x2[j]);
                            float yy2 = fminf(yi2, sm.y2[j]);
                            float ww = fmaxf(xx2 - xx1 + 1.0f, 0.0f);
                            float hh = fmaxf(yy2 - yy1 + 1.0f, 0.0f);
                            float inter = ww * hh;
                            float iou = inter / (ai + sm.area[j] - inter);
                            if (iou > NMS_TH) sm.keep[j] = 0;
                        }
                    }
                }
                __syncthreads();
            }
        }

        // emit kept candidates + global histogram
        for (int p = tid; p < M; p += bd) {
            bool kept = fastpath ? ((sm.kw[p >> 6] >> (p & 63)) & 1ULL) : (bool)sm.keep[p];
            if (kept) {
                int f = c * NPROP + p;
                unsigned long long key = sm.key[p];
                unsigned sbits = (unsigned)(key >> 32);
                int n = (NPROP - 1) - (int)(key & 0xFFFFFFFFULL);
                int gp = atomicAdd(&g_pcnt, 1);
                g_plist[gp] = ((unsigned long long)sbits << 32) | (unsigned)(0x7FFFFFFF - f);
                atomicAdd(&g_hist[score_bin(sbits)], 1);
                g_cand_orig[f] = n;
                ((float4*)g_cand_box)[f] = make_float4(sm.x1[p], sm.y1[p], sm.x2[p], sm.y2[p]);
            }
        }
    }
    __threadfence();
    __syncthreads();
    if (tid == 0) atomicAdd(&g_done, 1);
}

// ---------- topk block ----------
__device__ void run_topk(TopkView& sm, int tid, float* __restrict__ d_out) {
    if (tid == 0) {
        while (poll_int(&g_done) < NC2) __nanosleep(100);
    }
    __syncthreads();
    __threadfence();

    int P = g_pcnt;
    if (P > NC2 * NPROP) P = NC2 * NPROP;

    if (tid < KDET) sm.top[tid] = 0ULL;
    if (tid == 0) { sm.B = 0; sm.cnt = 0; }

    // suffix-scan of global histogram (256 scan threads; barriers block-wide)
    int base = (tid & 255) * 4;
    int h0 = 0, h1 = 0, h2 = 0, h3 = 0;
    if (tid < 256) {
        h0 = g_hist[base]; h1 = g_hist[base + 1]; h2 = g_hist[base + 2]; h3 = g_hist[base + 3];
        sm.part[tid] = h0 + h1 + h2 + h3;
        // reset hist for next replay (sole consumer)
        g_hist[base] = 0; g_hist[base + 1] = 0; g_hist[base + 2] = 0; g_hist[base + 3] = 0;
    }
    __syncthreads();
    for (int st = 1; st < 256; st <<= 1) {
        int v = 0;
        if (tid < 256) v = sm.part[tid] + ((tid + st < 256) ? sm.part[tid + st] : 0);
        __syncthreads();
        if (tid < 256) sm.part[tid] = v;
        __syncthreads();
    }
    if (tid < 256) {
        int T = (tid < 255) ? sm.part[tid + 1] : 0;
        int s3 = T + h3, s2 = s3 + h2, s1 = s2 + h1, s0 = s1 + h0;
        if (s0 >= KDET && s1 < KDET) sm.B = base;
        if (s1 >= KDET && s2 < KDET) sm.B = base + 1;
        if (s2 >= KDET && s3 < KDET) sm.B = base + 2;
        if (s3 >= KDET && T  < KDET) sm.B = base + 3;
    }
    __syncthreads();
    const int B = sm.B;

    // collect candidates in bins >= B
    for (int i = tid; i < P; i += NTHR) {
        unsigned long long key = g_plist[i];
        if (score_bin((unsigned)(key >> 32)) >= B) {
            int pos = atomicAdd(&sm.cnt, 1);
            if (pos < 2048) sm.key[pos] = key;
        }
    }
    __syncthreads();
    int cnt = sm.cnt;

    if (cnt <= 512) {
        // rank-order survivors; ranks < KDET are the outputs
        for (int i = tid; i < cnt; i += NTHR) {
            unsigned long long k = sm.key[i];
            int r = 0;
            for (int j = 0; j < cnt; j++) r += (sm.key[j] > k);
            if (r < KDET) sm.top[r] = k;
        }
        __syncthreads();
    } else if (cnt <= 2048) {
        int Sp = 128; while (Sp < cnt) Sp <<= 1;
        for (int i = cnt + tid; i < Sp; i += NTHR) sm.key[i] = 0ULL;
        __syncthreads();
        bitonic_desc(sm.key, Sp, tid, NTHR);
        if (tid < KDET) sm.top[tid] = sm.key[tid];
        __syncthreads();
    } else {
        // pathological tie overflow: exact chunked-carry over all candidates
        for (int i = tid; i < 2048; i += NTHR) sm.key[i] = (i < P) ? g_plist[i] : 0ULL;
        __syncthreads();
        bitonic_desc(sm.key, 2048, tid, NTHR);
        int pos = 2048;
        while (pos < P) {
            int c2 = P - pos; if (c2 > 1920) c2 = 1920;
            for (int i = tid; i < 1920; i += NTHR)
                sm.key[128 + i] = (i < c2) ? g_plist[pos + i] : 0ULL;
            __syncthreads();
            bitonic_desc(sm.key, 2048, tid, NTHR);
            pos += 1920;
        }
        if (tid < KDET) sm.top[tid] = sm.key[tid];
        __syncthreads();
    }

    // reset topk-owned counters for next replay (all consumers done)
    if (tid == 0) { g_pcnt = 0; g_done = 0; }

    // publish selection FIRST so feat blocks start, then write outputs
    unsigned long long key = 0ULL;
    float sc = 0.0f; int label = 0; int orig = -1;
    float4 bx = make_float4(0.f, 0.f, 0.f, 0.f);
    if (tid < KDET) {
        key = sm.top[tid];
        if (key) {
            sc = __uint_as_float((unsigned)(key >> 32));
            int f = 0x7FFFFFFF - (int)(key & 0xFFFFFFFFULL);
            bx = ((const float4*)g_cand_box)[f];
            label = (f >> 10) + 1;
            orig = g_cand_orig[f];
        }
        g_sel_orig[tid] = orig;
    }
    __threadfence();
    __syncthreads();
    if (tid == 0) atomicExch(&g_feat_flag, 1);

    if (tid < KDET) {
        d_out[tid * 4 + 0] = bx.x;
        d_out[tid * 4 + 1] = bx.y;
        d_out[tid * 4 + 2] = bx.z;
        d_out[tid * 4 + 3] = bx.w;
        d_out[KDET * 4 + tid] = sc;
        d_out[KDET * 4 + KDET + KDET * FDIM + tid] = (float)label;
    }
}

// ---------- feat block ----------
__device__ void run_feat(int k, int tid,
                         const float* __restrict__ features, float* __restrict__ d_out) {
    if (tid == 0) {
        while (poll_int(&g_feat_flag) == 0) __nanosleep(100);
    }
    __syncthreads();
    __threadfence();
    int orig = g_sel_orig[k];
    float4* dst = (float4*)(d_out + KDET * 4 + KDET + (size_t)k * FDIM);
    if (tid < 256) {
        if (orig >= 0) {
            const float4* src = (const float4*)(features + (size_t)orig * FDIM);
            dst[tid] = __ldg(src + tid);
        } else {
            dst[tid] = make_float4(0.f, 0.f, 0.f, 0.f);
        }
    }
}

// ---------- single kernel: rowstats + class-NMS + top-K + feature gather ----------
__global__ void __launch_bounds__(NTHR, 1)
everything_kernel(const float* __restrict__ logits,
                  const float* __restrict__ box_reg,
                  const float* __restrict__ proposals,
                  const float* __restrict__ features,
                  float* __restrict__ d_out) {
    __shared__ SMemU sm;
    const int bid = blockIdx.x, tid = threadIdx.x;

    // Phase 0: blocks 0..63 compute row softmax (warp per row, 16 warps/block)
    if (bid < NSTAT) {
        const int row  = bid * 16 + (tid >> 5);
        const int lane = tid & 31;
        const float* lp = logits + (size_t)row * NCLS;
        float l0 = lp[lane];
        float l1 = lp[lane + 32];
        float l2 = (lane < NCLS - 64) ? lp[lane + 64] : -3.4e38f;
        float mx = fmaxf(fmaxf(l0, l1), l2);
        for (int o = 16; o; o >>= 1) mx = fmaxf(mx, __shfl_xor_sync(0xffffffffu, mx, o));
        float e0 = expf(l0 - mx);
        float e1 = expf(l1 - mx);
        float e2 = (lane < NCLS - 64) ? expf(l2 - mx) : 0.0f;
        float sum = e0 + e1 + e2;
        for (int o = 16; o; o >>= 1) sum += __shfl_xor_sync(0xffffffffu, sum, o);
        g_probsT[lane * NPROP + row]        = e0 / sum;
        g_probsT[(lane + 32) * NPROP + row] = e1 / sum;
        if (lane < NCLS - 64) g_probsT[(lane + 64) * NPROP + row] = e2 / sum;
        __threadfence();
        __syncthreads();
        if (tid == 0) atomicAdd(&g_stats_done, 1);
    }

    // Phase 1: role dispatch
    if (bid < NC2) {
        run_class_nms(sm.nms, bid, tid, box_reg, proposals);
    } else if (bid == NC2) {
        run_topk(sm.tk, tid, d_out);
    } else {
        run_feat(bid - NC2 - 1, tid, features, d_out);
    }

    // Phase 2: last block out resets cross-replay state
    __syncthreads();
    if (tid == 0) {
        int v = atomicAdd(&g_exit, 1);
        if (v == NC2 + KDET) {          // 181st block
            g_stats_done = 0;
            g_feat_flag = 0;
            __threadfence();
            atomicExch(&g_exit, 0);
        }
    }
}

// ---------- launch ----------
extern "C" void kernel_launch(void* const* d_in, const int* in_sizes, int n_in,
                              void* d_out, int out_size) {
    const float* logits  = (const float*)d_in[0];   // [N, 81]
    const float* box_reg = (const float*)d_in[1];   // [N, 324]
    const float* props   = (const float*)d_in[2];   // [N, 4]
    const float* feats   = (const float*)d_in[3];   // [N, 1024]
    float* out = (float*)d_out;

    everything_kernel<<<NC2 + 1 + KDET, NTHR>>>(logits, box_reg, props, feats, out);
}